// round 15
// baseline (speedup 1.0000x reference)
#include <cuda_runtime.h>
#include <cuda_fp16.h>
#include <cstdint>

// ---------------------------------------------------------------------------
// ConvCapsuleLayer3D via fp16 mma.sync m16n8k16 (f32 accumulate):
//   prep_kernel : (fused) x -> g_xpad2 half2 padded volume, W -> A-fragments
//   conv_mma    : implicit GEMM. CTA = 64oc x 128pos, 256 thr, 3 CTAs/SM
//                 (24 warps/SM, 6/SMSP). Warp tile 32oc x 32pos (acc 32 regs).
//                 Halo in smem, A-fragments L1-resident LDG.128, barrier-free.
//   routing     : fused 3-iter sigmoid routing, fp16 votes (R5 version)
// ---------------------------------------------------------------------------

#define KTOT 432
#define NQ   216
#define PADC 39304     // 34^3
#define PADZ 1156
#define PADY 34

// halo strides (half2 units): [ch2(8)][zp(3)][yp(6)][xp(34)]
#define H_CI 612       // 3*6*34
#define H_KD 204
#define H_KH 34
#define HALO_W 4896

__device__ __half    g_votes[2 * 32768 * 1024];       // 134 MB
__device__ uint32_t  g_xpad2[8 * 8 * PADC];           // 10 MB half2 pairs
__device__ uint4     g_wfrag16[27 * 16 * 32];         // 221 KB A fragments

// conv smem: tbl[224] ints + halo[4896] words
#define OFF_HALO    224
#define SMEM_WORDS  (224 + 4896)
#define SMEM_BYTES  (SMEM_WORDS * 4)    // 20480

#define PAD_BLOCKS  ((8 * 8 * PADC + 255) / 256)   // 9826
#define WF_BLOCKS   ((27 * 16 * 32 + 255) / 256)   // 54

// ---------------------------------------------------------------------------
// prep: pad (blocks [0, PAD_BLOCKS)) + wfrag (blocks [PAD_BLOCKS, +WF_BLOCKS))
// ---------------------------------------------------------------------------
__global__ void prep_kernel(const float* __restrict__ X,
                            const float* __restrict__ W) {
    if (blockIdx.x < PAD_BLOCKS) {
        int idx = blockIdx.x * 256 + threadIdx.x;
        if (idx >= 8 * 8 * PADC) return;
        int nb = idx / (8 * PADC);
        int r  = idx - nb * (8 * PADC);
        int ch2 = r / PADC;
        int pp  = r - ch2 * PADC;
        int zp = pp / PADZ;  pp -= zp * PADZ;
        int yp = pp / PADY;
        int xp = pp - yp * PADY;
        int z = zp - 1, y = yp - 1, x = xp - 1;
        float v0 = 0.f, v1 = 0.f;
        if ((unsigned)z < 32u && (unsigned)y < 32u && (unsigned)x < 32u) {
            int pos = (z << 10) + (y << 5) + x;
            const float* src = X + ((size_t)(nb * 16 + ch2 * 2) << 15) + pos;
            v0 = src[0];
            v1 = src[32768];
        }
        __half2 h = __floats2half2_rn(v0, v1);
        g_xpad2[idx] = *(uint32_t*)&h;
    } else {
        int i = (blockIdx.x - PAD_BLOCKS) * 256 + threadIdx.x;
        if (i >= 27 * 16 * 32) return;
        int lane = i & 31;
        int m16  = (i >> 5) & 15;
        int ks   = i >> 9;
        int gid = lane >> 2, tig = lane & 3;
        uint32_t v[4];
        #pragma unroll
        for (int j = 0; j < 4; ++j) {
            int m = m16 * 16 + gid + ((j & 1) ? 8 : 0);
            int q = ks * 8 + tig + ((j >= 2) ? 4 : 0);
            int cihalf = q / 27;
            int tap    = q - cihalf * 27;
            int k0 = (2 * cihalf) * 27 + tap;
            __half2 h = __floats2half2_rn(W[m * KTOT + k0], W[m * KTOT + k0 + 27]);
            v[j] = *(uint32_t*)&h;
        }
        g_wfrag16[i] = make_uint4(v[0], v[1], v[2], v[3]);
    }
}

// ---------------------------------------------------------------------------
// conv: grid (256 [z,y-eighth], 8 [nb], 4 [mq]), 256 threads, 3 CTAs/SM
// warp tile 32oc x 32pos; 8 warps = (wm 2) x (wn 4); 27 k16-steps
// ---------------------------------------------------------------------------
__global__ void __launch_bounds__(256, 3)
conv_mma_kernel() {
    extern __shared__ uint32_t sm[];
    int*      tbl  = (int*)sm;
    uint32_t* halo = sm + OFF_HALO;

    const int tid  = threadIdx.x;
    const int w    = tid >> 5, lane = tid & 31;
    const int gid  = lane >> 2, tig = lane & 3;
    const int wm   = w >> 2;            // 0..1 (32 oc each)
    const int wn   = w & 3;             // 0..3 (32 pos each)

    const int bx = blockIdx.x;          // 0..255
    const int nb = blockIdx.y;          // 0..7
    const int mq = blockIdx.z;          // 0..3 (64-oc quarter)
    const int z  = bx >> 3, y0 = (bx & 7) * 4;

    // pair -> halo offset table
    for (int q = tid; q < NQ; q += 256) {
        int cihalf = q / 27;
        int tap    = q - cihalf * 27;
        int kd = tap / 9;  int rr = tap - kd * 9;
        int kh = rr / 3;   int kw = rr - kh * 3;
        tbl[q] = cihalf * H_CI + kd * H_KD + kh * H_KH + kw;
    }
    // halo: 8 ch2 x zp[z..z+2] x yp[y0..y0+5] x xp[0..33]
    {
        const uint32_t* xsrc = g_xpad2 + nb * (8 * PADC) + z * PADZ + y0 * PADY;
        for (int i = tid; i < HALO_W; i += 256) {
            int row = i / 34;
            int x   = i - row * 34;
            int ch2 = row / 18;
            int rr  = row - ch2 * 18;
            int zp  = rr / 6;
            int yp  = rr - zp * 6;
            halo[ch2 * H_CI + zp * H_KD + yp * H_KH + x] =
                xsrc[ch2 * PADC + zp * PADZ + yp * PADY + x];
        }
    }
    __syncthreads();

    int posoff[4];
    #pragma unroll
    for (int nt = 0; nt < 4; ++nt) {
        int ncol = wn * 32 + nt * 8 + gid;     // 0..127
        posoff[nt] = (ncol >> 5) * H_KH + (ncol & 31);
    }

    float acc[2][4][4];
    #pragma unroll
    for (int a = 0; a < 2; ++a)
        #pragma unroll
        for (int b = 0; b < 4; ++b)
            #pragma unroll
            for (int c = 0; c < 4; ++c) acc[a][b][c] = 0.f;

    // m16 global index base = mq*4 + wm*2
    const uint4* wf = g_wfrag16 + (size_t)(mq * 4 + wm * 2) * 32 + lane;

    #pragma unroll 3
    for (int ks = 0; ks < 27; ++ks) {
        const int q0 = tbl[ks * 8 + tig];
        const int q1 = tbl[ks * 8 + tig + 4];
        uint4 A[2];
        #pragma unroll
        for (int mi = 0; mi < 2; ++mi)
            A[mi] = wf[(ks * 16 + mi) * 32];
        #pragma unroll
        for (int nt = 0; nt < 4; ++nt) {
            uint32_t b0 = halo[q0 + posoff[nt]];
            uint32_t b1 = halo[q1 + posoff[nt]];
            #pragma unroll
            for (int mi = 0; mi < 2; ++mi) {
                asm volatile(
                    "mma.sync.aligned.m16n8k16.row.col.f32.f16.f16.f32 "
                    "{%0,%1,%2,%3}, {%4,%5,%6,%7}, {%8,%9}, {%0,%1,%2,%3};"
                    : "+f"(acc[mi][nt][0]), "+f"(acc[mi][nt][1]),
                      "+f"(acc[mi][nt][2]), "+f"(acc[mi][nt][3])
                    : "r"(A[mi].x), "r"(A[mi].y), "r"(A[mi].z), "r"(A[mi].w),
                      "r"(b0), "r"(b1));
            }
        }
    }

    // epilogue: fp16 votes[b][p][ic*256+oc] (scattered, measured-fastest)
    const int b_ = nb >> 2, ic_ = nb & 3;
    #pragma unroll
    for (int mi = 0; mi < 2; ++mi) {
        const int oc = mq * 64 + wm * 32 + mi * 16 + gid;
        #pragma unroll
        for (int nt = 0; nt < 4; ++nt) {
            const int posl = wn * 32 + nt * 8 + tig * 2;
            const int y = y0 + (posl >> 5);
            const int x = posl & 31;
            const int p = (z << 10) | (y << 5) | x;
            __half* dst = g_votes + (((size_t)((b_ << 15) + p)) << 10)
                        + ic_ * 256 + oc;
            dst[0]        = __float2half_rn(acc[mi][nt][0]);
            dst[8]        = __float2half_rn(acc[mi][nt][2]);
            dst[1024]     = __float2half_rn(acc[mi][nt][1]);
            dst[1024 + 8] = __float2half_rn(acc[mi][nt][3]);
        }
    }
}

// ---------------------------------------------------------------------------
// routing: warp = position, lane = (nc, quarter), 8 atoms/lane, fp16 votes
// ---------------------------------------------------------------------------
__global__ void __launch_bounds__(512, 2)
routing_kernel(const float* __restrict__ bias, float* __restrict__ out) {
    __shared__ float s[256][17];

    const int lane = threadIdx.x & 31;
    const int warp = threadIdx.x >> 5;
    const int blk  = blockIdx.x;
    const int b    = blk >> 11;
    const int p0   = (blk & 2047) * 16;
    const int p    = p0 + warp;
    const int nc   = lane >> 2, q = lane & 3;

    const __half* vb = g_votes + (((size_t)((b << 15) + p)) << 10) + nc * 32 + q * 8;
    float v[4][8];
    #pragma unroll
    for (int ic = 0; ic < 4; ++ic) {
        uint4 raw = *(const uint4*)(vb + ic * 256);
        float2 f;
        f = __half22float2(*(__half2*)&raw.x); v[ic][0] = f.x; v[ic][1] = f.y;
        f = __half22float2(*(__half2*)&raw.y); v[ic][2] = f.x; v[ic][3] = f.y;
        f = __half22float2(*(__half2*)&raw.z); v[ic][4] = f.x; v[ic][5] = f.y;
        f = __half22float2(*(__half2*)&raw.w); v[ic][6] = f.x; v[ic][7] = f.y;
    }
    float bb[8];
    {
        float4 a = *(const float4*)(bias + nc * 32 + q * 8);
        float4 c = *(const float4*)(bias + nc * 32 + q * 8 + 4);
        bb[0] = a.x; bb[1] = a.y; bb[2] = a.z; bb[3] = a.w;
        bb[4] = c.x; bb[5] = c.y; bb[6] = c.z; bb[7] = c.w;
    }

    float lgt[4] = {1.f, 1.f, 1.f, 1.f};
    float act[8];

    #pragma unroll
    for (int it = 0; it < 3; ++it) {
        float r[4];
        #pragma unroll
        for (int ic = 0; ic < 4; ++ic)
            r[ic] = 1.0f / (1.0f + __expf(-lgt[ic]));

        float pre[8], sql = 0.f;
        #pragma unroll
        for (int j = 0; j < 8; ++j) {
            float pv = bb[j];
            #pragma unroll
            for (int ic = 0; ic < 4; ++ic) pv = fmaf(r[ic], v[ic][j], pv);
            pre[j] = pv;
            sql = fmaf(pv, pv, sql);
        }
        sql += __shfl_xor_sync(0xFFFFFFFFu, sql, 1);
        sql += __shfl_xor_sync(0xFFFFFFFFu, sql, 2);
        float scale = sql / ((1.0f + sql) * sqrtf(sql + 1e-9f));
        #pragma unroll
        for (int j = 0; j < 8; ++j) act[j] = pre[j] * scale;

        if (it < 2) {
            #pragma unroll
            for (int ic = 0; ic < 4; ++ic) {
                float d = 0.f;
                #pragma unroll
                for (int j = 0; j < 8; ++j) d = fmaf(v[ic][j], act[j], d);
                d += __shfl_xor_sync(0xFFFFFFFFu, d, 1);
                d += __shfl_xor_sync(0xFFFFFFFFu, d, 2);
                lgt[ic] += d;
            }
        }
    }

    #pragma unroll
    for (int j = 0; j < 8; ++j) s[nc * 32 + q * 8 + j][warp] = act[j];
    __syncthreads();

    const int c  = threadIdx.x & 15;
    const int rw = threadIdx.x >> 4;
    #pragma unroll
    for (int rr = 0; rr < 8; ++rr) {
        int row = rr * 32 + rw;
        out[((size_t)(b * 256 + row) << 15) + p0 + c] = s[row][c];
    }
}

// ---------------------------------------------------------------------------
extern "C" void kernel_launch(void* const* d_in, const int* in_sizes, int n_in,
                              void* d_out, int out_size) {
    const float* x = (const float*)d_in[0];
    const float* W = (const float*)d_in[1];
    const float* b = (const float*)d_in[2];
    float* out = (float*)d_out;

    cudaFuncSetAttribute(conv_mma_kernel,
                         cudaFuncAttributeMaxDynamicSharedMemorySize, SMEM_BYTES);

    prep_kernel<<<PAD_BLOCKS + WF_BLOCKS, 256>>>(x, W);
    dim3 cgrid(256, 8, 4);
    conv_mma_kernel<<<cgrid, 256, SMEM_BYTES>>>();
    routing_kernel<<<4096, 512>>>(b, out);
}

// round 16
// speedup vs baseline: 1.1131x; 1.1131x over previous
#include <cuda_runtime.h>
#include <cuda_fp16.h>
#include <cstdint>

// ---------------------------------------------------------------------------
// ConvCapsuleLayer3D via fp16 mma.sync m16n8k16 (f32 accumulate):
//   pad_kernel   : x -> g_xpad2 half2(ch even, ch odd) padded volume
//   wfrag_kernel : W -> m16n8k16 A-fragments; K permuted by channel pairing
//                  AND kd-major tap ordering (bank-conflict avoidance)
//   conv_mma     : implicit GEMM, CTA = 128oc x 256pos (512 thr, R5 shape),
//                  K=432 (27 k16 steps). Halo resident in smem; A-fragments
//                  L1-resident LDG.128. Tap order makes each B-fragment's 4
//                  LDS offsets land in distinct mod-32 bank clusters
//                  ({~0,~20,~8} word-offsets) -> conflict degree 4 -> 2.
//   routing      : fused 3-iter sigmoid routing, fp16 votes
// ---------------------------------------------------------------------------

#define KTOT 432
#define NQ   216
#define PADC 39304     // 34^3
#define PADZ 1156
#define PADY 34

// halo strides (half2 units): [ch2(8)][zp(3)][yp(10)][xp(34)]
#define H_CI 1020      // 3*10*34
#define H_KD 340
#define H_KH 34

__device__ __half    g_votes[2 * 32768 * 1024];       // 134 MB
__device__ uint32_t  g_xpad2[8 * 8 * PADC];           // 10 MB half2 pairs
__device__ uint4     g_wfrag16[27 * 16 * 32];         // 221 KB A fragments

// conv smem: tbl[224] ints then halo[16320] uint32 (half2)
#define SM_HALO     224
#define SMEM_WORDS  (224 + 16320)
#define SMEM_BYTES  (SMEM_WORDS * 4)

// q -> (cihalf, kd, kh, kw) with kd-major tap ordering within each cihalf.
// MUST be identical in wfrag_kernel and conv tbl build.
__device__ __forceinline__ void decode_q(int q, int& cihalf,
                                         int& kd, int& kh, int& kw) {
    cihalf = q / 27;
    int j  = q - cihalf * 27;
    kd     = j % 3;            // cycle kd fastest: offsets jump ~{0,+20,+8} mod 32
    int r  = j / 3;            // 0..8
    kh     = r / 3;
    kw     = r - kh * 3;
}

// ---------------------------------------------------------------------------
__global__ void pad_kernel(const float* __restrict__ X) {
    int idx = blockIdx.x * 256 + threadIdx.x;
    if (idx >= 8 * 8 * PADC) return;
    int nb = idx / (8 * PADC);
    int r  = idx - nb * (8 * PADC);
    int ch2 = r / PADC;
    int pp  = r - ch2 * PADC;
    int zp = pp / PADZ;  pp -= zp * PADZ;
    int yp = pp / PADY;
    int xp = pp - yp * PADY;
    int z = zp - 1, y = yp - 1, x = xp - 1;
    float v0 = 0.f, v1 = 0.f;
    if ((unsigned)z < 32u && (unsigned)y < 32u && (unsigned)x < 32u) {
        int pos = (z << 10) + (y << 5) + x;
        const float* src = X + ((size_t)(nb * 16 + ch2 * 2) << 15) + pos;
        v0 = src[0];
        v1 = src[32768];
    }
    __half2 h = __floats2half2_rn(v0, v1);
    g_xpad2[idx] = *(uint32_t*)&h;
}

// A fragments: i = ks*512 + m16*32 + lane; 4 half2 per thread.
__global__ void wfrag_kernel(const float* __restrict__ W) {
    int i = blockIdx.x * 256 + threadIdx.x;
    if (i >= 27 * 16 * 32) return;
    int lane = i & 31;
    int m16  = (i >> 5) & 15;
    int ks   = i >> 9;
    int gid = lane >> 2, tig = lane & 3;
    uint32_t v[4];
    #pragma unroll
    for (int j = 0; j < 4; ++j) {
        int m = m16 * 16 + gid + ((j & 1) ? 8 : 0);
        int q = ks * 8 + tig + ((j >= 2) ? 4 : 0);
        int cihalf, kd, kh, kw;
        decode_q(q, cihalf, kd, kh, kw);
        int tap = kd * 9 + kh * 3 + kw;
        int k0  = (2 * cihalf) * 27 + tap;
        __half2 h = __floats2half2_rn(W[m * KTOT + k0], W[m * KTOT + k0 + 27]);
        v[j] = *(uint32_t*)&h;
    }
    g_wfrag16[i] = make_uint4(v[0], v[1], v[2], v[3]);
}

// ---------------------------------------------------------------------------
// conv: grid (128 [z,y-quarter], 8 [nb], 2 [mt]), 512 threads
// warp tile 64oc x 32pos; 16 warps = (wm 2) x (wn 8); 27 k16-steps
// ---------------------------------------------------------------------------
__global__ void __launch_bounds__(512, 1)
conv_mma_kernel() {
    extern __shared__ uint32_t sm[];
    int*      tbl  = (int*)sm;
    uint32_t* halo = sm + SM_HALO;

    const int tid  = threadIdx.x;
    const int w    = tid >> 5, lane = tid & 31;
    const int gid  = lane >> 2, tig = lane & 3;
    const int wm   = w >> 3;
    const int wn   = w & 7;

    const int bx = blockIdx.x;
    const int nb = blockIdx.y;
    const int mt = blockIdx.z;
    const int z  = bx >> 2, y0 = (bx & 3) * 8;

    // pair-index -> halo offset table (kd-major permutation, matches wfrag)
    for (int q = tid; q < NQ; q += 512) {
        int cihalf, kd, kh, kw;
        decode_q(q, cihalf, kd, kh, kw);
        tbl[q] = cihalf * H_CI + kd * H_KD + kh * H_KH + kw;
    }
    // halo: 8 cihalf x zp[z..z+2] x yp[y0..y0+9] x xp[0..33]
    {
        const uint32_t* xsrc = g_xpad2 + nb * (8 * PADC) + z * PADZ + y0 * PADY;
        for (int i = tid; i < 16320; i += 512) {
            int row = i / 34;
            int x   = i - row * 34;
            int ch2 = row / 30;
            int rr  = row - ch2 * 30;
            int zp  = rr / 10;
            int yp  = rr - zp * 10;
            halo[ch2 * H_CI + zp * H_KD + yp * H_KH + x] =
                xsrc[ch2 * PADC + zp * PADZ + yp * PADY + x];
        }
    }
    __syncthreads();

    int posoff[4];
    #pragma unroll
    for (int nt = 0; nt < 4; ++nt) {
        int ncol = wn * 32 + nt * 8 + gid;
        posoff[nt] = (ncol >> 5) * H_KH + (ncol & 31);
    }

    float acc[4][4][4];
    #pragma unroll
    for (int a = 0; a < 4; ++a)
        #pragma unroll
        for (int b = 0; b < 4; ++b)
            #pragma unroll
            for (int c = 0; c < 4; ++c) acc[a][b][c] = 0.f;

    const uint4* wf = g_wfrag16 + (size_t)(mt * 8 + wm * 4) * 32 + lane;

    #pragma unroll 3
    for (int ks = 0; ks < 27; ++ks) {
        const int q0 = tbl[ks * 8 + tig];
        const int q1 = tbl[ks * 8 + tig + 4];
        uint4 A[4];
        #pragma unroll
        for (int mi = 0; mi < 4; ++mi)
            A[mi] = wf[(ks * 16 + mi) * 32];
        #pragma unroll
        for (int nt = 0; nt < 4; ++nt) {
            uint32_t b0 = halo[q0 + posoff[nt]];
            uint32_t b1 = halo[q1 + posoff[nt]];
            #pragma unroll
            for (int mi = 0; mi < 4; ++mi) {
                asm volatile(
                    "mma.sync.aligned.m16n8k16.row.col.f32.f16.f16.f32 "
                    "{%0,%1,%2,%3}, {%4,%5,%6,%7}, {%8,%9}, {%0,%1,%2,%3};"
                    : "+f"(acc[mi][nt][0]), "+f"(acc[mi][nt][1]),
                      "+f"(acc[mi][nt][2]), "+f"(acc[mi][nt][3])
                    : "r"(A[mi].x), "r"(A[mi].y), "r"(A[mi].z), "r"(A[mi].w),
                      "r"(b0), "r"(b1));
            }
        }
    }

    // epilogue: fp16 votes[b][p][ic*256+oc] (R5 layout)
    const int b_ = nb >> 2, ic_ = nb & 3;
    #pragma unroll
    for (int mi = 0; mi < 4; ++mi) {
        const int oc = mt * 128 + wm * 64 + mi * 16 + gid;
        #pragma unroll
        for (int nt = 0; nt < 4; ++nt) {
            const int posl = wn * 32 + nt * 8 + tig * 2;
            const int y = y0 + (posl >> 5);
            const int x = posl & 31;
            const int p = (z << 10) | (y << 5) | x;
            __half* dst = g_votes + (((size_t)((b_ << 15) + p)) << 10)
                        + ic_ * 256 + oc;
            dst[0]        = __float2half_rn(acc[mi][nt][0]);
            dst[8]        = __float2half_rn(acc[mi][nt][2]);
            dst[1024]     = __float2half_rn(acc[mi][nt][1]);
            dst[1024 + 8] = __float2half_rn(acc[mi][nt][3]);
        }
    }
}

// ---------------------------------------------------------------------------
// routing: warp = position, lane = (nc, quarter), 8 atoms/lane, fp16 votes
// ---------------------------------------------------------------------------
__global__ void __launch_bounds__(512, 2)
routing_kernel(const float* __restrict__ bias, float* __restrict__ out) {
    __shared__ float s[256][17];

    const int lane = threadIdx.x & 31;
    const int warp = threadIdx.x >> 5;
    const int blk  = blockIdx.x;
    const int b    = blk >> 11;
    const int p0   = (blk & 2047) * 16;
    const int p    = p0 + warp;
    const int nc   = lane >> 2, q = lane & 3;

    const __half* vb = g_votes + (((size_t)((b << 15) + p)) << 10) + nc * 32 + q * 8;
    float v[4][8];
    #pragma unroll
    for (int ic = 0; ic < 4; ++ic) {
        uint4 raw = *(const uint4*)(vb + ic * 256);
        float2 f;
        f = __half22float2(*(__half2*)&raw.x); v[ic][0] = f.x; v[ic][1] = f.y;
        f = __half22float2(*(__half2*)&raw.y); v[ic][2] = f.x; v[ic][3] = f.y;
        f = __half22float2(*(__half2*)&raw.z); v[ic][4] = f.x; v[ic][5] = f.y;
        f = __half22float2(*(__half2*)&raw.w); v[ic][6] = f.x; v[ic][7] = f.y;
    }
    float bb[8];
    {
        float4 a = *(const float4*)(bias + nc * 32 + q * 8);
        float4 c = *(const float4*)(bias + nc * 32 + q * 8 + 4);
        bb[0] = a.x; bb[1] = a.y; bb[2] = a.z; bb[3] = a.w;
        bb[4] = c.x; bb[5] = c.y; bb[6] = c.z; bb[7] = c.w;
    }

    float lgt[4] = {1.f, 1.f, 1.f, 1.f};
    float act[8];

    #pragma unroll
    for (int it = 0; it < 3; ++it) {
        float r[4];
        #pragma unroll
        for (int ic = 0; ic < 4; ++ic)
            r[ic] = 1.0f / (1.0f + __expf(-lgt[ic]));

        float pre[8], sql = 0.f;
        #pragma unroll
        for (int j = 0; j < 8; ++j) {
            float pv = bb[j];
            #pragma unroll
            for (int ic = 0; ic < 4; ++ic) pv = fmaf(r[ic], v[ic][j], pv);
            pre[j] = pv;
            sql = fmaf(pv, pv, sql);
        }
        sql += __shfl_xor_sync(0xFFFFFFFFu, sql, 1);
        sql += __shfl_xor_sync(0xFFFFFFFFu, sql, 2);
        float scale = sql / ((1.0f + sql) * sqrtf(sql + 1e-9f));
        #pragma unroll
        for (int j = 0; j < 8; ++j) act[j] = pre[j] * scale;

        if (it < 2) {
            #pragma unroll
            for (int ic = 0; ic < 4; ++ic) {
                float d = 0.f;
                #pragma unroll
                for (int j = 0; j < 8; ++j) d = fmaf(v[ic][j], act[j], d);
                d += __shfl_xor_sync(0xFFFFFFFFu, d, 1);
                d += __shfl_xor_sync(0xFFFFFFFFu, d, 2);
                lgt[ic] += d;
            }
        }
    }

    #pragma unroll
    for (int j = 0; j < 8; ++j) s[nc * 32 + q * 8 + j][warp] = act[j];
    __syncthreads();

    const int c  = threadIdx.x & 15;
    const int rw = threadIdx.x >> 4;
    #pragma unroll
    for (int rr = 0; rr < 8; ++rr) {
        int row = rr * 32 + rw;
        out[((size_t)(b * 256 + row) << 15) + p0 + c] = s[row][c];
    }
}

// ---------------------------------------------------------------------------
extern "C" void kernel_launch(void* const* d_in, const int* in_sizes, int n_in,
                              void* d_out, int out_size) {
    const float* x = (const float*)d_in[0];
    const float* W = (const float*)d_in[1];
    const float* b = (const float*)d_in[2];
    float* out = (float*)d_out;

    cudaFuncSetAttribute(conv_mma_kernel,
                         cudaFuncAttributeMaxDynamicSharedMemorySize, SMEM_BYTES);

    pad_kernel<<<(8 * 8 * PADC + 255) / 256, 256>>>(x);
    wfrag_kernel<<<(27 * 16 * 32 + 255) / 256, 256>>>(W);
    dim3 cgrid(128, 8, 2);
    conv_mma_kernel<<<cgrid, 512, SMEM_BYTES>>>();
    routing_kernel<<<4096, 512>>>(b, out);
}